// round 1
// baseline (speedup 1.0000x reference)
#include <cuda_runtime.h>
#include <cuda_bf16.h>
#include <cstdint>

// Problem constants
#define BATCH   8192
#define KBITS   4096
#define KW      128        // 4096 bits = 128 u32 words
#define N12     4096
#define N3      1024
#define BN_EPS  1e-5

// ---------------- scratch (device globals; allocation is forbidden) -------
__device__ uint32_t g_Abits[2][BATCH * KW];          // ping-pong activation bitplanes (2 x 4MB)
__device__ uint32_t g_W0b[N12 * KW];                 // W0 column bitplanes (2MB)
__device__ uint32_t g_W1b[N12 * KW];                 // W1 column bitplanes (2MB)
__device__ uint32_t g_W2b[N3  * KW];                 // W2 column bitplanes (0.5MB)
__device__ int16_t  g_s[BATCH * N12];                // s values (64MB, reused per layer; layer3 col-major)
__device__ int                 g_colsum[N12];
__device__ unsigned long long  g_colsq[N12];
__device__ int                 g_colmax[N12];
__device__ float               g_rg[N12];            // gamma * rsqrt(var+eps) per column
__device__ float               g_invZ[N3];

// ---------------- binarize x: bit = (x >= 0.5) ---------------------------
__global__ void bp_binx(const float* __restrict__ x) {
    int t = blockIdx.x * blockDim.x + threadIdx.x;
    int warp = t >> 5, lane = t & 31;               // warp in [0, 8192*128)
    int row = warp >> 7, word = warp & 127;
    float v = x[row * KBITS + (word << 5) + lane];
    unsigned bits = __ballot_sync(0xFFFFFFFFu, v >= 0.5f);
    if (lane == 0) g_Abits[0][warp] = bits;
}

// ---------------- binarize W columns: bit = (w >= 0) ----------------------
// W row-major [K=4096][N]; output Wb[col][kword]. 32x32 tile transpose in smem.
__global__ void bp_binw(const float* __restrict__ W, int which, int N) {
    __shared__ float tile[32][33];
    int j0 = blockIdx.x * 32, k0 = blockIdx.y * 32;
    tile[threadIdx.y][threadIdx.x] = W[(k0 + threadIdx.y) * N + j0 + threadIdx.x];
    __syncthreads();
    float v = tile[threadIdx.x][threadIdx.y];       // row k0+tx, col j0+ty
    unsigned bits = __ballot_sync(0xFFFFFFFFu, v >= 0.f);
    if (threadIdx.x == 0) {
        uint32_t* Wb = (which == 0) ? g_W0b : (which == 1) ? g_W1b : g_W2b;
        Wb[(j0 + threadIdx.y) * KW + (k0 >> 5)] = bits;
    }
}

// ---------------- zero the per-column stats -------------------------------
__global__ void bp_zero(int n) {
    int i = blockIdx.x * blockDim.x + threadIdx.x;
    if (i < n) { g_colsum[i] = 0; g_colsq[i] = 0ull; g_colmax[i] = (int)0x80000000; }
}

// ---------------- XNOR-popcount GEMM + fused column stats -----------------
// C[i][j] = 4096 - 2*popc(A[i] ^ B[j]); BM=BN=64, 256 threads, 4x4 per thread.
__global__ __launch_bounds__(256) void bp_gemm(int asel, int wsel, int N, int l3) {
    const uint32_t* __restrict__ Ab = g_Abits[asel];
    const uint32_t* __restrict__ Bb = (wsel == 0) ? g_W0b : (wsel == 1) ? g_W1b : g_W2b;

    __shared__ uint32_t As[64][16];
    __shared__ uint32_t Bs[64][17];
    __shared__ int      red[16][64];

    int t  = threadIdx.x;
    int tx = t & 15, ty = t >> 4;
    int rowBase = blockIdx.y * 64, colBase = blockIdx.x * 64;

    int acc[4][4];
#pragma unroll
    for (int i = 0; i < 4; i++)
#pragma unroll
        for (int j = 0; j < 4; j++) acc[i][j] = 0;

    for (int k0 = 0; k0 < KW; k0 += 16) {
#pragma unroll
        for (int e = 0; e < 4; e++) {
            int i = t + e * 256;
            int r = i >> 4, kw = i & 15;
            As[r][kw] = Ab[(rowBase + r) * KW + k0 + kw];
            Bs[r][kw] = Bb[(colBase + r) * KW + k0 + kw];
        }
        __syncthreads();
#pragma unroll
        for (int kw = 0; kw < 16; kw++) {
            uint32_t a0 = As[ty * 4 + 0][kw], a1 = As[ty * 4 + 1][kw];
            uint32_t a2 = As[ty * 4 + 2][kw], a3 = As[ty * 4 + 3][kw];
            uint32_t b0 = Bs[tx * 4 + 0][kw], b1 = Bs[tx * 4 + 1][kw];
            uint32_t b2 = Bs[tx * 4 + 2][kw], b3 = Bs[tx * 4 + 3][kw];
            acc[0][0] += __popc(a0 ^ b0); acc[0][1] += __popc(a0 ^ b1);
            acc[0][2] += __popc(a0 ^ b2); acc[0][3] += __popc(a0 ^ b3);
            acc[1][0] += __popc(a1 ^ b0); acc[1][1] += __popc(a1 ^ b1);
            acc[1][2] += __popc(a1 ^ b2); acc[1][3] += __popc(a1 ^ b3);
            acc[2][0] += __popc(a2 ^ b0); acc[2][1] += __popc(a2 ^ b1);
            acc[2][2] += __popc(a2 ^ b2); acc[2][3] += __popc(a2 ^ b3);
            acc[3][0] += __popc(a3 ^ b0); acc[3][1] += __popc(a3 ^ b1);
            acc[3][2] += __popc(a3 ^ b2); acc[3][3] += __popc(a3 ^ b3);
        }
        __syncthreads();
    }

    int sv[4][4];
#pragma unroll
    for (int i = 0; i < 4; i++)
#pragma unroll
        for (int j = 0; j < 4; j++) sv[i][j] = KBITS - 2 * acc[i][j];

    // write s (vectorized 8B stores)
    if (!l3) {
#pragma unroll
        for (int i = 0; i < 4; i++) {
            uint2 p;
            p.x = (uint16_t)sv[i][0] | ((uint32_t)(uint16_t)sv[i][1] << 16);
            p.y = (uint16_t)sv[i][2] | ((uint32_t)(uint16_t)sv[i][3] << 16);
            *(uint2*)&g_s[(size_t)(rowBase + ty * 4 + i) * N + colBase + tx * 4] = p;
        }
    } else {
#pragma unroll
        for (int j = 0; j < 4; j++) {
            uint2 p;
            p.x = (uint16_t)sv[0][j] | ((uint32_t)(uint16_t)sv[1][j] << 16);
            p.y = (uint16_t)sv[2][j] | ((uint32_t)(uint16_t)sv[3][j] << 16);
            *(uint2*)&g_s[(size_t)(colBase + tx * 4 + j) * BATCH + rowBase + ty * 4] = p;
        }
    }

    // per-thread column partials over the 4 rows it owns
    int psum[4], psq[4], pmax[4];
#pragma unroll
    for (int j = 0; j < 4; j++) {
        psum[j] = sv[0][j] + sv[1][j] + sv[2][j] + sv[3][j];
        psq[j]  = sv[0][j] * sv[0][j] + sv[1][j] * sv[1][j]
                + sv[2][j] * sv[2][j] + sv[3][j] * sv[3][j];
        int m = sv[0][j]; m = max(m, sv[1][j]); m = max(m, sv[2][j]); m = max(m, sv[3][j]);
        pmax[j] = m;
    }

    // block reduce across the 16 ty-rows, then global atomics
#pragma unroll
    for (int j = 0; j < 4; j++) red[ty][tx * 4 + j] = psum[j];
    __syncthreads();
    if (t < 64) {
        int s = 0;
#pragma unroll
        for (int q = 0; q < 16; q++) s += red[q][t];
        atomicAdd(&g_colsum[colBase + t], s);
    }
    __syncthreads();
#pragma unroll
    for (int j = 0; j < 4; j++) red[ty][tx * 4 + j] = psq[j];
    __syncthreads();
    if (t < 64) {
        int s = 0;
#pragma unroll
        for (int q = 0; q < 16; q++) s += red[q][t];
        atomicAdd(&g_colsq[colBase + t], (unsigned long long)s);
    }
    if (l3) {
        __syncthreads();
#pragma unroll
        for (int j = 0; j < 4; j++) red[ty][tx * 4 + j] = pmax[j];
        __syncthreads();
        if (t < 64) {
            int m = red[0][t];
#pragma unroll
            for (int q = 1; q < 16; q++) m = max(m, red[q][t]);
            atomicMax(&g_colmax[colBase + t], m);
        }
    }
}

// ---------------- per-column rg = gamma * rsqrt(var+eps) -------------------
__global__ void bp_colprep(int N, const float* __restrict__ gamma, int layer) {
    int j = blockIdx.x * blockDim.x + threadIdx.x;
    if (j < N) {
        double mu  = (double)g_colsum[j] / (double)BATCH;
        double var = (double)g_colsq[j] / (double)BATCH - mu * mu;
        g_rg[j] = (float)((double)gamma[layer] / sqrt(var + BN_EPS));
    }
}

// ---------------- binarize normalized activations for next layer ----------
// bit = ( (8192*s - colsum)*rg + 8192*beta >= 0 )  (exact for beta=0)
__global__ void bp_bins(int N, int dst, const float* __restrict__ beta, int layer) {
    int t = blockIdx.x * blockDim.x + threadIdx.x;
    int warp = t >> 5, lane = t & 31;
    int words = N >> 5;
    int row = warp / words, word = warp - row * words;
    int col = (word << 5) + lane;
    int s = g_s[(size_t)row * N + col];
    int num = s * BATCH - g_colsum[col];
    float v = (float)num * g_rg[col] + beta[layer] * (float)BATCH;
    unsigned bits = __ballot_sync(0xFFFFFFFFu, v >= 0.f);
    if (lane == 0) g_Abits[dst][row * words + word] = bits;
}

// ---------------- softmax denominator per column (s stored col-major) -----
__global__ void bp_softz() {
    int j = blockIdx.x;
    int t = threadIdx.x;
    float c = g_rg[j];
    int   m = g_colmax[j];
    const int16_t* col = &g_s[(size_t)j * BATCH];
    float acc = 0.f;
    for (int i = t; i < BATCH; i += 256)
        acc += expf(c * (float)(col[i] - m));
    __shared__ float rs[256];
    rs[t] = acc;
    __syncthreads();
    for (int o = 128; o > 0; o >>= 1) {
        if (t < o) rs[t] += rs[t + o];
        __syncthreads();
    }
    if (t == 0) g_invZ[j] = 1.f / rs[0];
}

// ---------------- transpose + exp writeout --------------------------------
__global__ void bp_writeout(float* __restrict__ out) {
    __shared__ short tile[32][33];
    int j0 = blockIdx.x * 32, i0 = blockIdx.y * 32;
    tile[threadIdx.y][threadIdx.x] =
        g_s[(size_t)(j0 + threadIdx.y) * BATCH + i0 + threadIdx.x];
    __syncthreads();
    int j = j0 + threadIdx.x;
    int i = i0 + threadIdx.y;
    float c = g_rg[j];
    int   m = g_colmax[j];
    float z = g_invZ[j];
    out[(size_t)i * N3 + j] = expf(c * (float)(tile[threadIdx.x][threadIdx.y] - m)) * z;
}

// ---------------- launch ---------------------------------------------------
extern "C" void kernel_launch(void* const* d_in, const int* in_sizes, int n_in,
                              void* d_out, int out_size) {
    const float* x     = (const float*)d_in[0];
    const float* W0    = (const float*)d_in[1];
    const float* W1    = (const float*)d_in[2];
    const float* W2    = (const float*)d_in[3];
    const float* gamma = (const float*)d_in[4];
    const float* beta  = (const float*)d_in[5];
    float* out = (float*)d_out;

    dim3 b32(32, 32);

    bp_binx<<<(BATCH * KW) / 8, 256>>>(x);
    bp_binw<<<dim3(N12 / 32, KBITS / 32), b32>>>(W0, 0, N12);
    bp_binw<<<dim3(N12 / 32, KBITS / 32), b32>>>(W1, 1, N12);
    bp_binw<<<dim3(N3  / 32, KBITS / 32), b32>>>(W2, 2, N3);

    // ---- layer 0 ----
    bp_zero<<<N12 / 256, 256>>>(N12);
    bp_gemm<<<dim3(N12 / 64, BATCH / 64), 256>>>(0, 0, N12, 0);
    bp_colprep<<<N12 / 256, 256>>>(N12, gamma, 0);
    bp_bins<<<(BATCH * (N12 / 32)) / 8, 256>>>(N12, 1, beta, 0);

    // ---- layer 1 ----
    bp_zero<<<N12 / 256, 256>>>(N12);
    bp_gemm<<<dim3(N12 / 64, BATCH / 64), 256>>>(1, 1, N12, 0);
    bp_colprep<<<N12 / 256, 256>>>(N12, gamma, 1);
    bp_bins<<<(BATCH * (N12 / 32)) / 8, 256>>>(N12, 0, beta, 1);

    // ---- layer 2 (col-major s, +colmax) ----
    bp_zero<<<N12 / 256, 256>>>(N12);
    bp_gemm<<<dim3(N3 / 64, BATCH / 64), 256>>>(0, 2, N3, 1);
    bp_colprep<<<N3 / 256, 256>>>(N3, gamma, 2);
    bp_softz<<<N3, 256>>>();
    bp_writeout<<<dim3(N3 / 32, BATCH / 32), b32>>>(out);
}